// round 15
// baseline (speedup 1.0000x reference)
#include <cuda_runtime.h>
#include <cuda_bf16.h>
#include <cstdint>

#define NTOT 32768
#define DSUB 128
#define SCB  1024
#define KCB  4
#define MT   64
#define NCHUNK 16
#define CHC  64
#define THREADS 128
#define NC   10
#define CAP  12
#define DELTA 3e-3f

#define IDX_CNT (NTOT*KCB)            /* 131072  */
#define ZQ_CNT  (NTOT*KCB*DSUB)       /* 16777216 */
#define SC_OFF  (IDX_CNT + 2*ZQ_CNT)  /* 33685504 */

// filter smem: A bf16 16KB | B0 16KB | B1 16KB | cns 4KB
#define SM_A    0
#define SM_B0   16384
#define SM_B1   32768
#define SM_CNS  49152
#define SMEM_BYTES (53248 + 128)

__device__ double g_loss;
__device__ float  g_counts[KCB*SCB];
__device__ float  g_cnorm[KCB*SCB];
__device__ __nv_bfloat16 g_bsw[KCB*SCB*DSUB];  // pre-swizzled 16KB tiles
__device__ int    g_ccnt[IDX_CNT];
__device__ int    g_cand[IDX_CNT*CAP];

__device__ __forceinline__ uint32_t smem_u32(const void* p) {
    uint32_t a;
    asm("{ .reg .u64 t; cvta.to.shared.u64 t, %1; cvt.u32.u64 %0, t; }" : "=r"(a) : "l"(p));
    return a;
}
__device__ __forceinline__ void cpa16(void* dst, const void* src) {
    unsigned sa = (unsigned)__cvta_generic_to_shared(dst);
    asm volatile("cp.async.cg.shared.global [%0], [%1], 16;" :: "r"(sa), "l"(src));
}
#define CPA_COMMIT() asm volatile("cp.async.commit_group;" ::: "memory")
#define CPA_WAIT(n)  asm volatile("cp.async.wait_group %0;" :: "n"(n) : "memory")

__device__ __forceinline__ void ldsm4(uint32_t* r, uint32_t addr) {
    asm volatile("ldmatrix.sync.aligned.m8n8.x4.shared.b16 {%0,%1,%2,%3}, [%4];"
        : "=r"(r[0]), "=r"(r[1]), "=r"(r[2]), "=r"(r[3]) : "r"(addr));
}
__device__ __forceinline__ void mma16816(float* d, const uint32_t* a, uint32_t b0, uint32_t b1) {
    asm volatile("mma.sync.aligned.m16n8k16.row.col.f32.bf16.bf16.f32 "
        "{%0,%1,%2,%3}, {%4,%5,%6,%7}, {%8,%9}, {%0,%1,%2,%3};"
        : "+f"(d[0]), "+f"(d[1]), "+f"(d[2]), "+f"(d[3])
        : "r"(a[0]), "r"(a[1]), "r"(a[2]), "r"(a[3]), "r"(b0), "r"(b1));
}

// ---------------- init ----------------
__global__ void init_kernel(const float* __restrict__ cb) {
    int t = blockIdx.x*blockDim.x + threadIdx.x;
    int stride = blockDim.x*gridDim.x;
    if (t == 0) g_loss = 0.0;
    if (t < KCB*SCB) {
        g_counts[t] = 0.f;
        // ||c||^2: strict sequential ascending d, UNFUSED (matches reference)
        const float* r = cb + (size_t)t*DSUB;
        float s = 0.f;
        #pragma unroll 8
        for (int i = 0; i < DSUB; i++) { float v = r[i]; s = __fadd_rn(s, __fmul_rn(v, v)); }
        g_cnorm[t] = s;
    }
    for (int o = t; o < IDX_CNT; o += stride) g_ccnt[o] = 0;
    const int tot = KCB*SCB*DSUB;
    for (int o = t; o < tot; o += stride) {
        int d = o & (DSUB-1);
        int s = (o >> 7) & (SCB-1);
        int k = o >> 17;
        int tile = k*NCHUNK + (s >> 6);
        int row = s & 63;
        int swz = (d >> 3) ^ (row & 7);
        uint32_t byte = (uint32_t)row*256 + (swz << 4) + ((2*d) & 15);
        g_bsw[(size_t)tile*8192 + (byte >> 1)] = __float2bfloat16(cb[((size_t)(k*SCB + s))*DSUB + d]);
    }
}

__global__ void dummy_kernel() {}

// ---------------- phase 1: MMA filter -> candidate lists ----------------
__global__ __launch_bounds__(THREADS, 4)
void filter_kernel(const float* __restrict__ ze) {
    extern __shared__ char smem[];
    const uint32_t sb = smem_u32(smem);
    const int tid  = threadIdx.x;
    const int wid  = tid >> 5;
    const int lane = tid & 31;
    const int k  = blockIdx.y;
    const int n0 = blockIdx.x * MT;
    float* cns = (float*)(smem + SM_CNS);

    {
        const char* src = (const char*)(g_bsw + (size_t)(k*NCHUNK)*8192);
        #pragma unroll
        for (int i = 0; i < 8; i++) { int o = (tid + i*128)*16; cpa16(smem + SM_B0 + o, src + o); }
        CPA_COMMIT();
    }
    {
        const float4* src = (const float4*)(g_cnorm + k*SCB);
        float4* dst = (float4*)cns;
        dst[tid]       = src[tid];
        dst[tid + 128] = src[tid + 128];
    }
    #pragma unroll
    for (int it = 0; it < 16; it++) {
        int row = it*4 + wid;
        const float* zr = ze + (size_t)(n0 + row)*512 + k*DSUB + 4*lane;
        float4 v = *(const float4*)zr;
        uint32_t p0, p1;
        asm("cvt.rn.satfinite.bf16x2.f32 %0, %1, %2;" : "=r"(p0) : "f"(v.y), "f"(v.x));
        asm("cvt.rn.satfinite.bf16x2.f32 %0, %1, %2;" : "=r"(p1) : "f"(v.w), "f"(v.z));
        int swz = ((lane >> 1) ^ (row & 7));
        uint32_t byte = (uint32_t)row*256 + (swz << 4) + (lane & 1)*8;
        *(uint2*)(smem + SM_A + byte) = make_uint2(p0, p1);
    }
    __syncthreads();

    uint32_t afr[8][4];
    {
        int r  = wid*16 + (lane & 7) + ((lane >> 3) & 1)*8;
        #pragma unroll
        for (int s = 0; s < 8; s++) {
            int kb = s*32 + ((lane >> 4) & 1)*16;
            int c2 = (kb >> 4) ^ (r & 7);
            ldsm4(afr[s], sb + SM_A + r*256 + (c2 << 4));
        }
    }

    float runmin[2] = {3.402823466e38f, 3.402823466e38f};
    int   ncnt[2] = {0, 0};
    bool  ovf[2] = {false, false};
    float cV[2][NC]; int cI[2][NC];

    #pragma unroll 1
    for (int c = 0; c < NCHUNK; c++) {
        CPA_WAIT(0);
        __syncthreads();
        if (c + 1 < NCHUNK) {
            const char* src = (const char*)(g_bsw + (size_t)(k*NCHUNK + c + 1)*8192);
            char* dst = smem + (((c + 1) & 1) ? SM_B1 : SM_B0);
            #pragma unroll
            for (int i = 0; i < 8; i++) { int o = (tid + i*128)*16; cpa16(dst + o, src + o); }
            CPA_COMMIT();
        }
        uint32_t bb = sb + ((c & 1) ? SM_B1 : SM_B0);

        float acc[8][4];
        #pragma unroll
        for (int j2 = 0; j2 < 8; j2++) { acc[j2][0]=0.f; acc[j2][1]=0.f; acc[j2][2]=0.f; acc[j2][3]=0.f; }

        #pragma unroll
        for (int s = 0; s < 8; s++) {
            #pragma unroll
            for (int jq = 0; jq < 4; jq++) {
                int r  = (2*jq + ((lane >> 4) & 1))*8 + (lane & 7);
                int kb = s*32 + ((lane >> 3) & 1)*16;
                int ch = (kb >> 4) ^ (r & 7);
                uint32_t bf[4];
                ldsm4(bf, bb + r*256 + (ch << 4));
                mma16816(acc[2*jq],     afr[s], bf[0], bf[1]);
                mma16816(acc[2*jq + 1], afr[s], bf[2], bf[3]);
            }
        }

        float chm[2] = {3.402823466e38f, 3.402823466e38f};
        #pragma unroll
        for (int j2 = 0; j2 < 8; j2++) {
            int colb = c*CHC + j2*8 + 2*(lane & 3);
            float cn0 = cns[colb], cn1 = cns[colb + 1];
            #pragma unroll
            for (int h = 0; h < 2; h++) {
                float s0 = __fmaf_rn(-2.f, acc[j2][2*h],     cn0);
                float s1 = __fmaf_rn(-2.f, acc[j2][2*h + 1], cn1);
                acc[j2][2*h]     = s0;
                acc[j2][2*h + 1] = s1;
                chm[h] = fminf(chm[h], fminf(s0, s1));
            }
        }
        // TRUE quad row-chunk-min (quad = lane bits 0-1)
        #pragma unroll
        for (int h = 0; h < 2; h++) {
            chm[h] = fminf(chm[h], __shfl_xor_sync(0xffffffffu, chm[h], 1));
            chm[h] = fminf(chm[h], __shfl_xor_sync(0xffffffffu, chm[h], 2));
            runmin[h] = fminf(runmin[h], chm[h]);
        }

        #pragma unroll
        for (int j2 = 0; j2 < 8; j2++) {
            int colb = c*CHC + j2*8 + 2*(lane & 3);
            #pragma unroll
            for (int h = 0; h < 2; h++) {
                #pragma unroll
                for (int e = 0; e < 2; e++) {
                    float sc = acc[j2][2*h + e];
                    if (sc <= runmin[h] + DELTA) {
                        int si = colb + e;
                        if (ncnt[h] < NC) { cV[h][ncnt[h]] = sc; cI[h][ncnt[h]] = si; ncnt[h]++; }
                        else {
                            int w = 0;
                            #pragma unroll
                            for (int i2 = 0; i2 < NC; i2++)
                                if (cV[h][i2] <= runmin[h] + DELTA) { cV[h][w] = cV[h][i2]; cI[h][w] = cI[h][i2]; w++; }
                            ncnt[h] = w;
                            if (w < NC) { cV[h][w] = sc; cI[h][w] = si; ncnt[h] = w + 1; }
                            else ovf[h] = true;
                        }
                    }
                }
            }
        }
    }

    // write surviving candidates (re-filtered vs final true row min)
    #pragma unroll
    for (int h = 0; h < 2; h++) {
        float gm = runmin[h];   // already quad-true
        unsigned ofl = ovf[h] ? 1u : 0u;
        ofl |= __shfl_xor_sync(0xffffffffu, ofl, 1);
        ofl |= __shfl_xor_sync(0xffffffffu, ofl, 2);

        int row = wid*16 + (lane >> 2) + 8*h;
        int task = (n0 + row)*KCB + k;
        if (ofl && (lane & 3) == 0) atomicAdd(&g_ccnt[task], 1000);
        if (!ovf[h]) {
            for (int i = 0; i < ncnt[h]; i++) {
                if (cV[h][i] <= gm + DELTA) {
                    int slot = atomicAdd(&g_ccnt[task], 1);
                    if (slot < CAP) g_cand[task*CAP + slot] = cI[h][i];
                }
            }
        }
    }
}

// ---------------- phase 2: fused warp-per-task exact rescore + epilogue ----------------
__global__ __launch_bounds__(256)
void exact_epi_kernel(const float* __restrict__ ze, const float* __restrict__ cb,
                      float* __restrict__ out) {
    __shared__ float red[8];
    int gt = blockIdx.x*blockDim.x + threadIdx.x;
    int t = gt >> 5;               // task 0..131071
    int lane = gt & 31;
    int wwid = threadIdx.x >> 5;
    int n = t >> 2, k = t & 3;
    const float* zr = ze + (size_t)n*512 + k*DSUB;
    // X = ||x||^2: strict sequential ascending, UNFUSED (all lanes identical, broadcast loads)
    float X = 0.f;
    #pragma unroll 8
    for (int d4 = 0; d4 < 32; d4++) {
        float4 v = *(const float4*)(zr + 4*d4);
        X = __fadd_rn(X, __fmul_rn(v.x, v.x));
        X = __fadd_rn(X, __fmul_rn(v.y, v.y));
        X = __fadd_rn(X, __fmul_rn(v.z, v.z));
        X = __fadd_rn(X, __fmul_rn(v.w, v.w));
    }
    const float* cbk = cb + (size_t)k*SCB*DSUB;
    const float* cn  = g_cnorm + k*SCB;
    int cnt = g_ccnt[t];
    float bD = 3.402823466e38f;
    int   bS = 1 << 30;
    if (cnt <= CAP) {
        if (lane < cnt) {
            int s = g_cand[t*CAP + lane];
            const float* cr = cbk + (size_t)s*DSUB;
            float a = 0.f;
            #pragma unroll 8
            for (int d4 = 0; d4 < 32; d4++) {
                float4 xv = *(const float4*)(zr + 4*d4);
                float4 cv = *(const float4*)(cr + 4*d4);
                a = __fmaf_rn(xv.x, cv.x, a);
                a = __fmaf_rn(xv.y, cv.y, a);
                a = __fmaf_rn(xv.z, cv.z, a);
                a = __fmaf_rn(xv.w, cv.w, a);
            }
            bD = __fadd_rn(__fsub_rn(X, __fmul_rn(2.f, a)), __ldg(cn + s));
            bS = s;
        }
    } else {
        // ~never: full exact scan, 32 codes per lane (lane-parallel)
        for (int q = 0; q < 32; q++) {
            int s = lane*32 + q;
            const float* cr = cbk + (size_t)s*DSUB;
            float a = 0.f;
            #pragma unroll 8
            for (int d4 = 0; d4 < 32; d4++) {
                float4 xv = *(const float4*)(zr + 4*d4);
                float4 cv = *(const float4*)(cr + 4*d4);
                a = __fmaf_rn(xv.x, cv.x, a);
                a = __fmaf_rn(xv.y, cv.y, a);
                a = __fmaf_rn(xv.z, cv.z, a);
                a = __fmaf_rn(xv.w, cv.w, a);
            }
            float dist = __fadd_rn(__fsub_rn(X, __fmul_rn(2.f, a)), __ldg(cn + s));
            if (dist < bD || (dist == bD && s < bS)) { bD = dist; bS = s; }
        }
    }
    // lexicographic warp reduce (lowest index on ties) — all lanes end with result
    #pragma unroll
    for (int off = 1; off < 32; off <<= 1) {
        float d2 = __shfl_xor_sync(0xffffffffu, bD, off);
        int   s2 = __shfl_xor_sync(0xffffffffu, bS, off);
        if (d2 < bD || (d2 == bD && s2 < bS)) { bD = d2; bS = s2; }
    }
    if (lane == 0) {
        out[t] = (float)bS;
        atomicAdd(&g_counts[k*SCB + bS], 1.0f);
    }

    // ---- fused epilogue: lane d4 handles float4 d4 of this task's row ----
    float lsum;
    {
        const float4* cv4 = (const float4*)(cbk + (size_t)bS*DSUB);
        float4 cv = __ldg(&cv4[lane]);
        float4 a  = *(const float4*)(zr + 4*lane);   // L1-hot from X loop
        float4 df, st;
        df.x = __fsub_rn(cv.x, a.x); st.x = __fadd_rn(a.x, df.x);
        df.y = __fsub_rn(cv.y, a.y); st.y = __fadd_rn(a.y, df.y);
        df.z = __fsub_rn(cv.z, a.z); st.z = __fadd_rn(a.z, df.z);
        df.w = __fsub_rn(cv.w, a.w); st.w = __fadd_rn(a.w, df.w);
        ((float4*)(out + IDX_CNT))[t*32 + lane]          = st;
        ((float4*)(out + IDX_CNT + ZQ_CNT))[t*32 + lane] = cv;
        lsum = df.x*df.x + df.y*df.y + df.z*df.z + df.w*df.w;
    }
    #pragma unroll
    for (int off = 16; off > 0; off >>= 1)
        lsum += __shfl_xor_sync(0xffffffffu, lsum, off);
    if (lane == 0) red[wwid] = lsum;
    __syncthreads();
    if (threadIdx.x == 0) {
        float s = 0.f;
        #pragma unroll
        for (int w = 0; w < 8; w++) s += red[w];
        atomicAdd(&g_loss, (double)s);
    }
}

__global__ void fin_kernel(float* __restrict__ out) {
    __shared__ double sh[512];
    int tid = threadIdx.x;
    int k = tid >> 7, j = tid & 127;
    double h = 0.0;
    for (int s = j; s < SCB; s += 128) {
        float cnt = g_counts[k*SCB + s];
        if (cnt > 0.f) {
            double p = (double)cnt / (double)NTOT;
            h -= p * log(p);
        }
    }
    sh[tid] = h;
    __syncthreads();
    for (int off = 64; off > 0; off >>= 1) {
        if (j < off) sh[tid] += sh[tid + off];
        __syncthreads();
    }
    if (tid == 0) {
        double perp = 0.0;
        for (int kk = 0; kk < KCB; kk++) perp += exp(sh[kk*128]);
        perp *= 0.25;
        double loss = g_loss / (double)ZQ_CNT;
        out[SC_OFF + 0] = (float)loss;
        out[SC_OFF + 1] = (float)loss;
        out[SC_OFF + 2] = (float)perp;
    }
}

extern "C" void kernel_launch(void* const* d_in, const int* in_sizes, int n_in,
                              void* d_out, int out_size) {
    const float* ze = (const float*)d_in[0];
    const float* cb = (const float*)d_in[1];
    if (n_in >= 2 && in_sizes[0] == KCB*SCB*DSUB && in_sizes[1] == NTOT*512) {
        const float* t = ze; ze = cb; cb = t;
    }
    float* out = (float*)d_out;
    (void)out_size;

    cudaFuncSetAttribute(filter_kernel, cudaFuncAttributeMaxDynamicSharedMemorySize, SMEM_BYTES);

    init_kernel<<<256, 256>>>(cb);
    dummy_kernel<<<1, 32>>>();
    dummy_kernel<<<1, 32>>>();
    filter_kernel<<<dim3(NTOT/MT, KCB), THREADS, SMEM_BYTES>>>(ze);
    exact_epi_kernel<<<IDX_CNT*32/256, 256>>>(ze, cb, out);
    fin_kernel<<<1, 512>>>(out);
}

// round 16
// speedup vs baseline: 1.7571x; 1.7571x over previous
#include <cuda_runtime.h>
#include <cuda_bf16.h>
#include <cstdint>

#define NTOT 32768
#define DSUB 128
#define SCB  1024
#define KCB  4
#define MT   64
#define NCHUNK 16
#define CHC  64
#define THREADS 128
#define NC   10
#define CAP  12
#define DELTA 3e-3f

#define IDX_CNT (NTOT*KCB)            /* 131072  */
#define ZQ_CNT  (NTOT*KCB*DSUB)       /* 16777216 */
#define SC_OFF  (IDX_CNT + 2*ZQ_CNT)  /* 33685504 */

// filter smem: A bf16 16KB | B0 16KB | B1 16KB | cns 4KB
#define SM_A    0
#define SM_B0   16384
#define SM_B1   32768
#define SM_CNS  49152
#define SMEM_BYTES (53248 + 128)

__device__ double g_loss;
__device__ float  g_counts[KCB*SCB];
__device__ float  g_cnorm[KCB*SCB];
__device__ __nv_bfloat16 g_bsw[KCB*SCB*DSUB];  // pre-swizzled 16KB tiles
__device__ int    g_ccnt[IDX_CNT];
__device__ int    g_cand[IDX_CNT*CAP];
__device__ int    g_sidx[IDX_CNT];

__device__ __forceinline__ uint32_t smem_u32(const void* p) {
    uint32_t a;
    asm("{ .reg .u64 t; cvta.to.shared.u64 t, %1; cvt.u32.u64 %0, t; }" : "=r"(a) : "l"(p));
    return a;
}
__device__ __forceinline__ void cpa16(void* dst, const void* src) {
    unsigned sa = (unsigned)__cvta_generic_to_shared(dst);
    asm volatile("cp.async.cg.shared.global [%0], [%1], 16;" :: "r"(sa), "l"(src));
}
#define CPA_COMMIT() asm volatile("cp.async.commit_group;" ::: "memory")
#define CPA_WAIT(n)  asm volatile("cp.async.wait_group %0;" :: "n"(n) : "memory")

__device__ __forceinline__ void ldsm4(uint32_t* r, uint32_t addr) {
    asm volatile("ldmatrix.sync.aligned.m8n8.x4.shared.b16 {%0,%1,%2,%3}, [%4];"
        : "=r"(r[0]), "=r"(r[1]), "=r"(r[2]), "=r"(r[3]) : "r"(addr));
}
__device__ __forceinline__ void mma16816(float* d, const uint32_t* a, uint32_t b0, uint32_t b1) {
    asm volatile("mma.sync.aligned.m16n8k16.row.col.f32.bf16.bf16.f32 "
        "{%0,%1,%2,%3}, {%4,%5,%6,%7}, {%8,%9}, {%0,%1,%2,%3};"
        : "+f"(d[0]), "+f"(d[1]), "+f"(d[2]), "+f"(d[3])
        : "r"(a[0]), "r"(a[1]), "r"(a[2]), "r"(a[3]), "r"(b0), "r"(b1));
}

// ---------------- init ----------------
__global__ void init_kernel(const float* __restrict__ cb) {
    int t = blockIdx.x*blockDim.x + threadIdx.x;
    int stride = blockDim.x*gridDim.x;
    if (t == 0) g_loss = 0.0;
    if (t < KCB*SCB) {
        g_counts[t] = 0.f;
        // ||c||^2: strict sequential ascending d, UNFUSED (matches reference)
        const float* r = cb + (size_t)t*DSUB;
        float s = 0.f;
        #pragma unroll 8
        for (int i = 0; i < DSUB; i++) { float v = r[i]; s = __fadd_rn(s, __fmul_rn(v, v)); }
        g_cnorm[t] = s;
    }
    for (int o = t; o < IDX_CNT; o += stride) g_ccnt[o] = 0;
    const int tot = KCB*SCB*DSUB;
    for (int o = t; o < tot; o += stride) {
        int d = o & (DSUB-1);
        int s = (o >> 7) & (SCB-1);
        int k = o >> 17;
        int tile = k*NCHUNK + (s >> 6);
        int row = s & 63;
        int swz = (d >> 3) ^ (row & 7);
        uint32_t byte = (uint32_t)row*256 + (swz << 4) + ((2*d) & 15);
        g_bsw[(size_t)tile*8192 + (byte >> 1)] = __float2bfloat16(cb[((size_t)(k*SCB + s))*DSUB + d]);
    }
}

__global__ void dummy_kernel() {}

// ---------------- phase 1: MMA filter -> candidate lists ----------------
__global__ __launch_bounds__(THREADS, 4)
void filter_kernel(const float* __restrict__ ze) {
    extern __shared__ char smem[];
    const uint32_t sb = smem_u32(smem);
    const int tid  = threadIdx.x;
    const int wid  = tid >> 5;
    const int lane = tid & 31;
    const int k  = blockIdx.y;
    const int n0 = blockIdx.x * MT;
    float* cns = (float*)(smem + SM_CNS);

    {
        const char* src = (const char*)(g_bsw + (size_t)(k*NCHUNK)*8192);
        #pragma unroll
        for (int i = 0; i < 8; i++) { int o = (tid + i*128)*16; cpa16(smem + SM_B0 + o, src + o); }
        CPA_COMMIT();
    }
    {
        const float4* src = (const float4*)(g_cnorm + k*SCB);
        float4* dst = (float4*)cns;
        dst[tid]       = src[tid];
        dst[tid + 128] = src[tid + 128];
    }
    #pragma unroll
    for (int it = 0; it < 16; it++) {
        int row = it*4 + wid;
        const float* zr = ze + (size_t)(n0 + row)*512 + k*DSUB + 4*lane;
        float4 v = *(const float4*)zr;
        uint32_t p0, p1;
        asm("cvt.rn.satfinite.bf16x2.f32 %0, %1, %2;" : "=r"(p0) : "f"(v.y), "f"(v.x));
        asm("cvt.rn.satfinite.bf16x2.f32 %0, %1, %2;" : "=r"(p1) : "f"(v.w), "f"(v.z));
        int swz = ((lane >> 1) ^ (row & 7));
        uint32_t byte = (uint32_t)row*256 + (swz << 4) + (lane & 1)*8;
        *(uint2*)(smem + SM_A + byte) = make_uint2(p0, p1);
    }
    __syncthreads();

    uint32_t afr[8][4];
    {
        int r  = wid*16 + (lane & 7) + ((lane >> 3) & 1)*8;
        #pragma unroll
        for (int s = 0; s < 8; s++) {
            int kb = s*32 + ((lane >> 4) & 1)*16;
            int c2 = (kb >> 4) ^ (r & 7);
            ldsm4(afr[s], sb + SM_A + r*256 + (c2 << 4));
        }
    }

    float runmin[2] = {3.402823466e38f, 3.402823466e38f};
    int   ncnt[2] = {0, 0};
    bool  ovf[2] = {false, false};
    float cV[2][NC]; int cI[2][NC];

    #pragma unroll 1
    for (int c = 0; c < NCHUNK; c++) {
        CPA_WAIT(0);
        __syncthreads();
        if (c + 1 < NCHUNK) {
            const char* src = (const char*)(g_bsw + (size_t)(k*NCHUNK + c + 1)*8192);
            char* dst = smem + (((c + 1) & 1) ? SM_B1 : SM_B0);
            #pragma unroll
            for (int i = 0; i < 8; i++) { int o = (tid + i*128)*16; cpa16(dst + o, src + o); }
            CPA_COMMIT();
        }
        uint32_t bb = sb + ((c & 1) ? SM_B1 : SM_B0);

        float acc[8][4];
        #pragma unroll
        for (int j2 = 0; j2 < 8; j2++) { acc[j2][0]=0.f; acc[j2][1]=0.f; acc[j2][2]=0.f; acc[j2][3]=0.f; }

        #pragma unroll
        for (int s = 0; s < 8; s++) {
            #pragma unroll
            for (int jq = 0; jq < 4; jq++) {
                int r  = (2*jq + ((lane >> 4) & 1))*8 + (lane & 7);
                int kb = s*32 + ((lane >> 3) & 1)*16;
                int ch = (kb >> 4) ^ (r & 7);
                uint32_t bf[4];
                ldsm4(bf, bb + r*256 + (ch << 4));
                mma16816(acc[2*jq],     afr[s], bf[0], bf[1]);
                mma16816(acc[2*jq + 1], afr[s], bf[2], bf[3]);
            }
        }

        float chm[2] = {3.402823466e38f, 3.402823466e38f};
        #pragma unroll
        for (int j2 = 0; j2 < 8; j2++) {
            int colb = c*CHC + j2*8 + 2*(lane & 3);
            float cn0 = cns[colb], cn1 = cns[colb + 1];
            #pragma unroll
            for (int h = 0; h < 2; h++) {
                float s0 = __fmaf_rn(-2.f, acc[j2][2*h],     cn0);
                float s1 = __fmaf_rn(-2.f, acc[j2][2*h + 1], cn1);
                acc[j2][2*h]     = s0;
                acc[j2][2*h + 1] = s1;
                chm[h] = fminf(chm[h], fminf(s0, s1));
            }
        }
        // TRUE quad row-chunk-min (quad = lane bits 0-1)
        #pragma unroll
        for (int h = 0; h < 2; h++) {
            chm[h] = fminf(chm[h], __shfl_xor_sync(0xffffffffu, chm[h], 1));
            chm[h] = fminf(chm[h], __shfl_xor_sync(0xffffffffu, chm[h], 2));
            runmin[h] = fminf(runmin[h], chm[h]);
        }

        #pragma unroll
        for (int j2 = 0; j2 < 8; j2++) {
            int colb = c*CHC + j2*8 + 2*(lane & 3);
            #pragma unroll
            for (int h = 0; h < 2; h++) {
                #pragma unroll
                for (int e = 0; e < 2; e++) {
                    float sc = acc[j2][2*h + e];
                    if (sc <= runmin[h] + DELTA) {
                        int si = colb + e;
                        if (ncnt[h] < NC) { cV[h][ncnt[h]] = sc; cI[h][ncnt[h]] = si; ncnt[h]++; }
                        else {
                            int w = 0;
                            #pragma unroll
                            for (int i2 = 0; i2 < NC; i2++)
                                if (cV[h][i2] <= runmin[h] + DELTA) { cV[h][w] = cV[h][i2]; cI[h][w] = cI[h][i2]; w++; }
                            ncnt[h] = w;
                            if (w < NC) { cV[h][w] = sc; cI[h][w] = si; ncnt[h] = w + 1; }
                            else ovf[h] = true;
                        }
                    }
                }
            }
        }
    }

    // write surviving candidates (re-filtered vs final true row min)
    #pragma unroll
    for (int h = 0; h < 2; h++) {
        float gm = runmin[h];   // already quad-true
        unsigned ofl = ovf[h] ? 1u : 0u;
        ofl |= __shfl_xor_sync(0xffffffffu, ofl, 1);
        ofl |= __shfl_xor_sync(0xffffffffu, ofl, 2);

        int row = wid*16 + (lane >> 2) + 8*h;
        int task = (n0 + row)*KCB + k;
        if (ofl && (lane & 3) == 0) atomicAdd(&g_ccnt[task], 1000);
        if (!ovf[h]) {
            for (int i = 0; i < ncnt[h]; i++) {
                if (cV[h][i] <= gm + DELTA) {
                    int slot = atomicAdd(&g_ccnt[task], 1);
                    if (slot < CAP) g_cand[task*CAP + slot] = cI[h][i];
                }
            }
        }
    }
}

// ---------------- phase 2: warp-per-task exact rescore (bit-exact) ----------------
__global__ __launch_bounds__(256)
void exact_kernel(const float* __restrict__ ze, const float* __restrict__ cb,
                  float* __restrict__ out) {
    int gt = blockIdx.x*blockDim.x + threadIdx.x;
    int t = gt >> 5;               // task 0..131071
    int lane = gt & 31;
    int n = t >> 2, k = t & 3;
    int cnt = g_ccnt[t];
    int bS;

    if (cnt == 1) {
        // single candidate from a superset containing the argmin => it IS the argmin
        bS = g_cand[t*CAP];
    } else {
        const float* zr = ze + (size_t)n*512 + k*DSUB;
        // X = ||x||^2: strict sequential ascending, UNFUSED (matches reference)
        float X = 0.f;
        #pragma unroll 8
        for (int d4 = 0; d4 < 32; d4++) {
            float4 v = *(const float4*)(zr + 4*d4);
            X = __fadd_rn(X, __fmul_rn(v.x, v.x));
            X = __fadd_rn(X, __fmul_rn(v.y, v.y));
            X = __fadd_rn(X, __fmul_rn(v.z, v.z));
            X = __fadd_rn(X, __fmul_rn(v.w, v.w));
        }
        const float* cbk = cb + (size_t)k*SCB*DSUB;
        const float* cn  = g_cnorm + k*SCB;
        float bD = 3.402823466e38f;
        bS = 1 << 30;
        if (cnt <= CAP) {
            if (lane < cnt) {
                int s = g_cand[t*CAP + lane];
                const float* cr = cbk + (size_t)s*DSUB;
                float a = 0.f;
                #pragma unroll 8
                for (int d4 = 0; d4 < 32; d4++) {
                    float4 xv = *(const float4*)(zr + 4*d4);
                    float4 cv = *(const float4*)(cr + 4*d4);
                    a = __fmaf_rn(xv.x, cv.x, a);
                    a = __fmaf_rn(xv.y, cv.y, a);
                    a = __fmaf_rn(xv.z, cv.z, a);
                    a = __fmaf_rn(xv.w, cv.w, a);
                }
                bD = __fadd_rn(__fsub_rn(X, __fmul_rn(2.f, a)), __ldg(cn + s));
                bS = s;
            }
        } else {
            // ~never: full exact scan, 32 codes per lane (lane-parallel)
            for (int q = 0; q < 32; q++) {
                int s = lane*32 + q;
                const float* cr = cbk + (size_t)s*DSUB;
                float a = 0.f;
                #pragma unroll 8
                for (int d4 = 0; d4 < 32; d4++) {
                    float4 xv = *(const float4*)(zr + 4*d4);
                    float4 cv = *(const float4*)(cr + 4*d4);
                    a = __fmaf_rn(xv.x, cv.x, a);
                    a = __fmaf_rn(xv.y, cv.y, a);
                    a = __fmaf_rn(xv.z, cv.z, a);
                    a = __fmaf_rn(xv.w, cv.w, a);
                }
                float dist = __fadd_rn(__fsub_rn(X, __fmul_rn(2.f, a)), __ldg(cn + s));
                if (dist < bD || (dist == bD && s < bS)) { bD = dist; bS = s; }
            }
        }
        // lexicographic warp reduce (lowest index on ties)
        #pragma unroll
        for (int off = 1; off < 32; off <<= 1) {
            float d2 = __shfl_xor_sync(0xffffffffu, bD, off);
            int   s2 = __shfl_xor_sync(0xffffffffu, bS, off);
            if (d2 < bD || (d2 == bD && s2 < bS)) { bD = d2; bS = s2; }
        }
    }
    if (lane == 0) {
        g_sidx[t] = bS;
        out[t] = (float)bS;
        atomicAdd(&g_counts[k*SCB + bS], 1.0f);
    }
}

// ---------------- phase 3: streaming epilogue ----------------
__global__ __launch_bounds__(256)
void epi_kernel(const float* __restrict__ ze, const float* __restrict__ cb,
                float* __restrict__ out) {
    __shared__ float red[8];
    const int tid = threadIdx.x;
    const int lane = tid & 31, wid = tid >> 5;
    const float4* ze4  = (const float4*)ze;
    float4* st4  = (float4*)(out + IDX_CNT);
    float4* all4 = (float4*)(out + IDX_CNT + ZQ_CNT);
    float lsum = 0.f;
    int stride = gridDim.x*blockDim.x;
    for (int g = blockIdx.x*blockDim.x + tid; g < ZQ_CNT/4; g += stride) {
        int task = g >> 5, d4 = g & 31, k = task & 3;
        int idx = __ldg(&g_sidx[task]);
        const float4* cv4 = (const float4*)(cb + ((size_t)(k*SCB + idx))*DSUB);
        float4 cv = __ldg(&cv4[d4]);
        float4 a  = __ldg(&ze4[g]);
        float4 df, st;
        df.x = __fsub_rn(cv.x, a.x); st.x = __fadd_rn(a.x, df.x);
        df.y = __fsub_rn(cv.y, a.y); st.y = __fadd_rn(a.y, df.y);
        df.z = __fsub_rn(cv.z, a.z); st.z = __fadd_rn(a.z, df.z);
        df.w = __fsub_rn(cv.w, a.w); st.w = __fadd_rn(a.w, df.w);
        st4[g]  = st;
        all4[g] = cv;
        lsum += df.x*df.x + df.y*df.y + df.z*df.z + df.w*df.w;
    }
    #pragma unroll
    for (int off = 16; off > 0; off >>= 1)
        lsum += __shfl_xor_sync(0xffffffffu, lsum, off);
    if (lane == 0) red[wid] = lsum;
    __syncthreads();
    if (tid == 0) {
        float s = 0.f;
        #pragma unroll
        for (int w = 0; w < 8; w++) s += red[w];
        atomicAdd(&g_loss, (double)s);
    }
}

__global__ void fin_kernel(float* __restrict__ out) {
    __shared__ double sh[512];
    int tid = threadIdx.x;
    int k = tid >> 7, j = tid & 127;
    double h = 0.0;
    for (int s = j; s < SCB; s += 128) {
        float cnt = g_counts[k*SCB + s];
        if (cnt > 0.f) {
            double p = (double)cnt / (double)NTOT;
            h -= p * log(p);
        }
    }
    sh[tid] = h;
    __syncthreads();
    for (int off = 64; off > 0; off >>= 1) {
        if (j < off) sh[tid] += sh[tid + off];
        __syncthreads();
    }
    if (tid == 0) {
        double perp = 0.0;
        for (int kk = 0; kk < KCB; kk++) perp += exp(sh[kk*128]);
        perp *= 0.25;
        double loss = g_loss / (double)ZQ_CNT;
        out[SC_OFF + 0] = (float)loss;
        out[SC_OFF + 1] = (float)loss;
        out[SC_OFF + 2] = (float)perp;
    }
}

extern "C" void kernel_launch(void* const* d_in, const int* in_sizes, int n_in,
                              void* d_out, int out_size) {
    const float* ze = (const float*)d_in[0];
    const float* cb = (const float*)d_in[1];
    if (n_in >= 2 && in_sizes[0] == KCB*SCB*DSUB && in_sizes[1] == NTOT*512) {
        const float* t = ze; ze = cb; cb = t;
    }
    float* out = (float*)d_out;
    (void)out_size;

    cudaFuncSetAttribute(filter_kernel, cudaFuncAttributeMaxDynamicSharedMemorySize, SMEM_BYTES);

    init_kernel<<<256, 256>>>(cb);
    dummy_kernel<<<1, 32>>>();
    dummy_kernel<<<1, 32>>>();
    filter_kernel<<<dim3(NTOT/MT, KCB), THREADS, SMEM_BYTES>>>(ze);
    exact_kernel<<<IDX_CNT*32/256, 256>>>(ze, cb, out);
    epi_kernel<<<4096, 256>>>(ze, cb, out);
    fin_kernel<<<1, 512>>>(out);
}